// round 15
// baseline (speedup 1.0000x reference)
#include <cuda_runtime.h>
#include <cuda_bf16.h>
#include <cstdint>

// Performer (FAVOR+) attention. k1: bf16 split 3-MMA. k2/k3: tf32 single-MMA.
// k3 retiled to 64-row CTAs (~80 regs -> 3 CTAs/SM). R10 base otherwise.

#define B_      64
#define N_      2048
#define D_      64
#define M_      266
#define MP_     288
#define NROWS_  (B_ * N_)
#define SCALE_  0.35355339059327373f
#define NORMC_  0.0625f
#define RATIO_  0.06131393394849658f
#define EPS_    1e-4f
#define CTXS_   ((size_t)B_ * 64 * MP_)

__device__ float    g_qdash[NROWS_ * MP_];
__device__ float    g_kdash[NROWS_ * MP_];
__device__ float    g_qnorm[NROWS_];
__device__ float    g_knorm[NROWS_];
__device__ float    g_qmax2[2 * NROWS_];
__device__ float    g_kpart[2048];
__device__ float    g_kmaxf;
__device__ float    g_ctxP[4 * B_ * 64 * MP_];
__device__ float    g_ksumP[4 * B_ * MP_];
__device__ float    g_ctx[B_ * 64 * MP_];
__device__ float    g_ksum[B_ * MP_];

// ---------------- helpers ----------------
__device__ __forceinline__ void mma_bf16(float* d, const uint32_t* a,
                                         uint32_t b0, uint32_t b1) {
    asm volatile(
        "mma.sync.aligned.m16n8k16.row.col.f32.bf16.bf16.f32 "
        "{%0,%1,%2,%3}, {%4,%5,%6,%7}, {%8,%9}, {%0,%1,%2,%3};\n"
        : "+f"(d[0]), "+f"(d[1]), "+f"(d[2]), "+f"(d[3])
        : "r"(a[0]), "r"(a[1]), "r"(a[2]), "r"(a[3]), "r"(b0), "r"(b1));
}
__device__ __forceinline__ void mma_tf32(float* d, const uint32_t* a,
                                         uint32_t b0, uint32_t b1) {
    asm volatile(
        "mma.sync.aligned.m16n8k8.row.col.f32.tf32.tf32.f32 "
        "{%0,%1,%2,%3}, {%4,%5,%6,%7}, {%8,%9}, {%0,%1,%2,%3};\n"
        : "+f"(d[0]), "+f"(d[1]), "+f"(d[2]), "+f"(d[3])
        : "r"(a[0]), "r"(a[1]), "r"(a[2]), "r"(a[3]), "r"(b0), "r"(b1));
}
__device__ __forceinline__ uint32_t to_tf32(float x) {
    uint32_t r;
    asm("cvt.rna.tf32.f32 %0, %1;" : "=r"(r) : "f"(x));
    return r;
}
__device__ __forceinline__ void split_pack(float x, float y, uint32_t& hi, uint32_t& lo) {
    __nv_bfloat16 hx = __float2bfloat16(x);
    __nv_bfloat16 hy = __float2bfloat16(y);
    __nv_bfloat16 lx = __float2bfloat16(x - __bfloat162float(hx));
    __nv_bfloat16 ly = __float2bfloat16(y - __bfloat162float(hy));
    hi = (uint32_t)__bfloat16_as_ushort(hx) | ((uint32_t)__bfloat16_as_ushort(hy) << 16);
    lo = (uint32_t)__bfloat16_as_ushort(lx) | ((uint32_t)__bfloat16_as_ushort(ly) << 16);
}
__device__ __forceinline__ uint32_t fenc(float x) {
    uint32_t u = __float_as_uint(x);
    return (u & 0x80000000u) ? ~u : (u | 0x80000000u);
}
__device__ __forceinline__ float fdec(uint32_t u) {
    return (u & 0x80000000u) ? __uint_as_float(u & 0x7FFFFFFFu) : __uint_as_float(~u);
}

// ---------------- K1: dash = SCALE * X @ P^T (bf16 3-MMA, R10 version) ---------
#define K1_AH 0
#define K1_AL 18432
#define K1_BH 36864
#define K1_BL 57600
#define K1_RM 78336
#define K1_SM 78848

__global__ __launch_bounds__(256)
void k1_proj(const float* __restrict__ Q, const float* __restrict__ K,
             const float* __restrict__ P) {
    extern __shared__ char sm[];
    uint32_t* Ah = (uint32_t*)(sm + K1_AH);
    uint32_t* Al = (uint32_t*)(sm + K1_AL);
    uint32_t* Bh = (uint32_t*)(sm + K1_BH);
    uint32_t* Bl = (uint32_t*)(sm + K1_BL);
    float*    OB = (float*)sm;
    uint32_t* rmaxU = (uint32_t*)(sm + K1_RM);

    const int tid = threadIdx.x, w = tid >> 5, l = tid & 31;
    const int g = l >> 2, t = l & 3;
    const int isq = (blockIdx.z == 0);
    const float* X = isq ? Q : K;
    const int row0 = blockIdx.x * 128;
    const int m0 = blockIdx.y * 144;
    const int r_off = (w & 3) * 32;
    const int f_off = (w >> 2) * 72;
    float* dash  = isq ? g_qdash : g_kdash;
    float* norms = isq ? g_qnorm : g_knorm;

    if (tid < 128) rmaxU[tid] = 0u;
    __syncthreads();

    const float4* X4 = (const float4*)X;
    for (int i = tid; i < 2048; i += 256) {
        const int r = i >> 4, c4 = i & 15;
        float4 v = X4[(size_t)(row0 + r) * 16 + c4];
        uint32_t h0, l0, h1, l1;
        split_pack(v.x, v.y, h0, l0);
        split_pack(v.z, v.w, h1, l1);
        Ah[r * 36 + 2 * c4] = h0; Ah[r * 36 + 2 * c4 + 1] = h1;
        Al[r * 36 + 2 * c4] = l0; Al[r * 36 + 2 * c4 + 1] = l1;
    }
    const float4* P4 = (const float4*)P;
    for (int i = tid; i < 2304; i += 256) {
        const int m = i >> 4, c4 = i & 15;
        float4 v = make_float4(0.f, 0.f, 0.f, 0.f);
        if (m0 + m < M_) v = P4[(size_t)(m0 + m) * 16 + c4];
        uint32_t h0, l0, h1, l1;
        split_pack(v.x * SCALE_, v.y * SCALE_, h0, l0);
        split_pack(v.z * SCALE_, v.w * SCALE_, h1, l1);
        Bh[m * 36 + 2 * c4] = h0; Bh[m * 36 + 2 * c4 + 1] = h1;
        Bl[m * 36 + 2 * c4] = l0; Bl[m * 36 + 2 * c4 + 1] = l1;
    }
    __syncthreads();

    if (blockIdx.y == 0 && tid < 128) {
        float s = 0.f;
        const float4* xr = X4 + (size_t)(row0 + tid) * 16;
#pragma unroll
        for (int c4 = 0; c4 < 16; c4++) {
            float4 v = xr[c4];
            s += v.x * v.x + v.y * v.y + v.z * v.z + v.w * v.w;
        }
        norms[row0 + tid] = NORMC_ * s;
    }

    float acc[2][9][4];
#pragma unroll
    for (int mi = 0; mi < 2; mi++)
#pragma unroll
        for (int ni = 0; ni < 9; ni++)
#pragma unroll
            for (int j = 0; j < 4; j++) acc[mi][ni][j] = 0.f;

#pragma unroll
    for (int kk = 0; kk < 4; kk++) {
        const int c = 8 * kk + t;
        uint32_t ah[2][4], al[2][4];
#pragma unroll
        for (int mi = 0; mi < 2; mi++) {
            const int rA = r_off + 16 * mi;
            ah[mi][0] = Ah[(rA + g) * 36 + c];
            ah[mi][1] = Ah[(rA + 8 + g) * 36 + c];
            ah[mi][2] = Ah[(rA + g) * 36 + c + 4];
            ah[mi][3] = Ah[(rA + 8 + g) * 36 + c + 4];
            al[mi][0] = Al[(rA + g) * 36 + c];
            al[mi][1] = Al[(rA + 8 + g) * 36 + c];
            al[mi][2] = Al[(rA + g) * 36 + c + 4];
            al[mi][3] = Al[(rA + 8 + g) * 36 + c + 4];
        }
#pragma unroll
        for (int ni = 0; ni < 9; ni++) {
            const int cw = (f_off + 8 * ni + g) * 36;
            uint32_t bh0 = Bh[cw + c], bh1 = Bh[cw + c + 4];
            uint32_t bl0 = Bl[cw + c], bl1 = Bl[cw + c + 4];
#pragma unroll
            for (int mi = 0; mi < 2; mi++) {
                mma_bf16(acc[mi][ni], ah[mi], bh0, bh1);
                mma_bf16(acc[mi][ni], ah[mi], bl0, bl1);
                mma_bf16(acc[mi][ni], al[mi], bh0, bh1);
            }
        }
    }

    float rmx[2][2] = {{-3.4e38f, -3.4e38f}, {-3.4e38f, -3.4e38f}};
#pragma unroll
    for (int mi = 0; mi < 2; mi++)
#pragma unroll
        for (int ni = 0; ni < 9; ni++) {
            const int cb = m0 + f_off + 8 * ni + 2 * t;
            if (cb < M_) {
                rmx[mi][0] = fmaxf(rmx[mi][0], acc[mi][ni][0]);
                rmx[mi][1] = fmaxf(rmx[mi][1], acc[mi][ni][2]);
            }
            if (cb + 1 < M_) {
                rmx[mi][0] = fmaxf(rmx[mi][0], acc[mi][ni][1]);
                rmx[mi][1] = fmaxf(rmx[mi][1], acc[mi][ni][3]);
            }
        }
#pragma unroll
    for (int mi = 0; mi < 2; mi++) {
        atomicMax(&rmaxU[r_off + 16 * mi + g], fenc(rmx[mi][0]));
        atomicMax(&rmaxU[r_off + 16 * mi + 8 + g], fenc(rmx[mi][1]));
    }

    __syncthreads();
#pragma unroll
    for (int mi = 0; mi < 2; mi++) {
        const int rl = r_off + 16 * mi + g;
#pragma unroll
        for (int ni = 0; ni < 9; ni++) {
            const int cl = f_off + 8 * ni + 2 * t;
            *(float2*)&OB[rl * 148 + cl]       = make_float2(acc[mi][ni][0], acc[mi][ni][1]);
            *(float2*)&OB[(rl + 8) * 148 + cl] = make_float2(acc[mi][ni][2], acc[mi][ni][3]);
        }
    }
    __syncthreads();

    for (int i = tid; i < 4608; i += 256) {
        const int r = i / 36, c4 = i - 36 * r;
        *(float4*)&dash[(size_t)(row0 + r) * MP_ + m0 + 4 * c4] =
            *(float4*)&OB[r * 148 + 4 * c4];
    }

    if (isq) {
        if (tid < 128)
            g_qmax2[blockIdx.y * NROWS_ + row0 + tid] = fdec(rmaxU[tid]);
    } else {
        if (tid < 32) {
            uint32_t u = max(max(rmaxU[tid], rmaxU[tid + 32]),
                             max(rmaxU[tid + 64], rmaxU[tid + 96]));
#pragma unroll
            for (int o = 16; o; o >>= 1)
                u = max(u, __shfl_xor_sync(0xffffffffu, u, o));
            if (tid == 0) g_kpart[blockIdx.y * 1024 + blockIdx.x] = fdec(u);
        }
    }
}

// ---------------- K1c: global k max ----------------
__global__ void k1c_kmax() {
    __shared__ float sm[256];
    float mx = -3.4e38f;
    for (int i = threadIdx.x; i < 2048; i += 256) mx = fmaxf(mx, g_kpart[i]);
    sm[threadIdx.x] = mx;
    __syncthreads();
    for (int s = 128; s; s >>= 1) {
        if (threadIdx.x < s) sm[threadIdx.x] = fmaxf(sm[threadIdx.x], sm[threadIdx.x + s]);
        __syncthreads();
    }
    if (threadIdx.x == 0) g_kmaxf = sm[0];
}

// ---------------- K2: ctxP[slice] = v^T @ kp (tf32, double-buffered) -----------
__global__ __launch_bounds__(192)
void k2_ctx(const float* __restrict__ v) {
    __shared__ uint32_t VA[2][64 * 20];
    __shared__ uint32_t KB[2][96 * 20];
    __shared__ float kss[96];

    const int tid = threadIdx.x, w = tid >> 5, l = tid & 31;
    const int g = l >> 2, t = l & 3;
    const int b = blockIdx.z;
    const int m0 = blockIdx.x * 96;
    const int slice = blockIdx.y;
    const int nbase = slice * 512;
    const int bN = b * N_;
    const float kmax = g_kmaxf;

    const int mloc = l + 32 * (w % 3);
    const int sgrp = w / 3;
    const int mglob = m0 + mloc;
    const bool mval = mglob < M_;
    const int vg = w >> 1;
    const int ve = l + 32 * (w & 1);

    const int e_off = (w & 1) * 32;
    const int m_off = (w >> 1) * 32;

    if (tid < 96) kss[tid] = 0.f;

    float acc[2][4][4];
#pragma unroll
    for (int mi = 0; mi < 2; mi++)
#pragma unroll
        for (int ni = 0; ni < 4; ni++)
#pragma unroll
            for (int j = 0; j < 4; j++) acc[mi][ni][j] = 0.f;
    float kslocal = 0.f;

    float pd0[4], pd1[4], pn0[4], pn1[4], pv0[4], pv1[4];
#pragma unroll
    for (int ii = 0; ii < 4; ii++) {
        const int n = nbase + 2 * (4 * sgrp + ii);
        pd0[ii] = g_kdash[(size_t)(bN + n) * MP_ + mglob];
        pd1[ii] = g_kdash[(size_t)(bN + n + 1) * MP_ + mglob];
        pn0[ii] = g_knorm[bN + n];
        pn1[ii] = g_knorm[bN + n + 1];
    }
    if (w < 4) {
#pragma unroll
        for (int ii = 0; ii < 4; ii++) {
            const int n = nbase + 2 * (4 * vg + ii);
            pv0[ii] = v[(size_t)(bN + n) * 64 + ve];
            pv1[ii] = v[(size_t)(bN + n + 1) * 64 + ve];
        }
    }

    for (int ck = 0; ck < 32; ck++) {
        const int cur = ck & 1;
        uint32_t* va = VA[cur];
        uint32_t* kb = KB[cur];

        float d0c[4], d1c[4], n0c[4], n1c[4], v0c[4], v1c[4];
#pragma unroll
        for (int ii = 0; ii < 4; ii++) {
            d0c[ii] = pd0[ii]; d1c[ii] = pd1[ii];
            n0c[ii] = pn0[ii]; n1c[ii] = pn1[ii];
            v0c[ii] = pv0[ii]; v1c[ii] = pv1[ii];
        }
        if (ck < 31) {
            const int nn = nbase + 16 * (ck + 1);
#pragma unroll
            for (int ii = 0; ii < 4; ii++) {
                const int n = nn + 2 * (4 * sgrp + ii);
                pd0[ii] = g_kdash[(size_t)(bN + n) * MP_ + mglob];
                pd1[ii] = g_kdash[(size_t)(bN + n + 1) * MP_ + mglob];
                pn0[ii] = g_knorm[bN + n];
                pn1[ii] = g_knorm[bN + n + 1];
            }
            if (w < 4) {
#pragma unroll
                for (int ii = 0; ii < 4; ii++) {
                    const int n = nn + 2 * (4 * vg + ii);
                    pv0[ii] = v[(size_t)(bN + n) * 64 + ve];
                    pv1[ii] = v[(size_t)(bN + n + 1) * 64 + ve];
                }
            }
        }
#pragma unroll
        for (int ii = 0; ii < 4; ii++) {
            const int i = 4 * sgrp + ii;
            float kp0 = mval ? RATIO_ * (__expf(d0c[ii] - n0c[ii] - kmax) + EPS_) : 0.f;
            float kp1 = mval ? RATIO_ * (__expf(d1c[ii] - n1c[ii] - kmax) + EPS_) : 0.f;
            kslocal += kp0 + kp1;
            *(uint2*)&kb[mloc * 20 + 2 * i] = make_uint2(to_tf32(kp0), to_tf32(kp1));
        }
        if (w < 4) {
#pragma unroll
            for (int ii = 0; ii < 4; ii++) {
                const int i = 4 * vg + ii;
                *(uint2*)&va[ve * 20 + 2 * i] = make_uint2(to_tf32(v0c[ii]), to_tf32(v1c[ii]));
            }
        }
        __syncthreads();
#pragma unroll
        for (int kk = 0; kk < 2; kk++) {
            const int c = 8 * kk + t;
            uint32_t a[2][4];
#pragma unroll
            for (int mi = 0; mi < 2; mi++) {
                const int eR = e_off + 16 * mi;
                a[mi][0] = va[(eR + g) * 20 + c];
                a[mi][1] = va[(eR + 8 + g) * 20 + c];
                a[mi][2] = va[(eR + g) * 20 + c + 4];
                a[mi][3] = va[(eR + 8 + g) * 20 + c + 4];
            }
#pragma unroll
            for (int ni = 0; ni < 4; ni++) {
                const int cw = (m_off + 8 * ni + g) * 20;
                uint32_t b0 = kb[cw + c], b1 = kb[cw + c + 4];
#pragma unroll
                for (int mi = 0; mi < 2; mi++)
                    mma_tf32(acc[mi][ni], a[mi], b0, b1);
            }
        }
    }

    atomicAdd(&kss[mloc], kslocal);
    __syncthreads();
    if (tid < 96) g_ksumP[((size_t)(slice * B_ + b)) * MP_ + m0 + tid] = kss[tid];

    float* base = g_ctxP + slice * CTXS_;
#pragma unroll
    for (int mi = 0; mi < 2; mi++) {
        const int e0 = e_off + 16 * mi + g;
#pragma unroll
        for (int ni = 0; ni < 4; ni++) {
            const int mc = m0 + m_off + 8 * ni + 2 * t;
            *(float2*)&base[((size_t)(b * 64 + e0)) * MP_ + mc] =
                make_float2(acc[mi][ni][0], acc[mi][ni][1]);
            *(float2*)&base[((size_t)(b * 64 + e0 + 8)) * MP_ + mc] =
                make_float2(acc[mi][ni][2], acc[mi][ni][3]);
        }
    }
}

// ---------------- KRED: ctx = sum(ctxP), ksum = sum(ksumP) ----------------------
__global__ void kred() {
    const int i = blockIdx.x * 256 + threadIdx.x;
    const float4* s0 = (const float4*)g_ctxP;
    float4 a = s0[i];
    float4 b = s0[i + CTXS_ / 4];
    float4 c = s0[i + 2 * (CTXS_ / 4)];
    float4 d = s0[i + 3 * (CTXS_ / 4)];
    ((float4*)g_ctx)[i] = make_float4(a.x + b.x + c.x + d.x, a.y + b.y + c.y + d.y,
                                      a.z + b.z + c.z + d.z, a.w + b.w + c.w + d.w);
    if (i < B_ * MP_ / 4) {
        const float4* k0 = (const float4*)g_ksumP;
        const int st = B_ * MP_ / 4;
        float4 e = k0[i], f = k0[i + st], g = k0[i + 2 * st], h = k0[i + 3 * st];
        ((float4*)g_ksum)[i] = make_float4(e.x + f.x + g.x + h.x, e.y + f.y + g.y + h.y,
                                           e.z + f.z + g.z + h.z, e.w + f.w + g.w + h.w);
    }
}

// ---------------- K3: out = (qp @ ctx^T) * dinv (tf32, 64-row CTAs) ------------
// 256 thr, 8 warps (4r x 2e), warp tile 16x32. ~80 regs -> 3 CTAs/SM.
#define K3_QP  0          // 2 x 9216
#define K3_CB  18432      // 2 x 9216
#define K3_DI  36864      // 256
#define K3_KS  37120      // 1152
#define K3_SM  38272

__global__ __launch_bounds__(256)
void k3_out(float* __restrict__ out) {
    extern __shared__ char sm3[];
    float* OB   = (float*)sm3;                 // union with QP/CB after loop
    float* dinv = (float*)(sm3 + K3_DI);
    float* ksum_s = (float*)(sm3 + K3_KS);

    const int tid = threadIdx.x, w = tid >> 5, l = tid & 31;
    const int g = l >> 2, t = l & 3;
    const int b = blockIdx.y;
    const int r0 = blockIdx.x * 64;
    const int bN = b * N_;

    const int sr = tid >> 2, sq = tid & 3;     // staging: 4 threads per row, 8 m each

    const int gr = bN + r0 + sr;
    const float qn = g_qnorm[gr];
    const float qm = fmaxf(g_qmax2[gr], g_qmax2[NROWS_ + gr]);

    const int r_off = (w & 3) * 16;
    const int e_off = (w >> 2) * 32;

    for (int i = tid; i < MP_; i += 256) ksum_s[i] = g_ksum[b * MP_ + i];
    __syncthreads();

    float acc[4][4];
#pragma unroll
    for (int ni = 0; ni < 4; ni++)
#pragma unroll
        for (int j = 0; j < 4; j++) acc[ni][j] = 0.f;
    float Dpart = 0.f;

    const float* qsrc = g_qdash + (size_t)gr * MP_ + 8 * sq;
    const float* csrc = g_ctx + ((size_t)(b * 64 + sr)) * MP_ + 8 * sq;

    float4 pq[2], pc[2];
#pragma unroll
    for (int j = 0; j < 2; j++) pq[j] = *(const float4*)(qsrc + 4 * j);
#pragma unroll
    for (int j = 0; j < 2; j++) pc[j] = *(const float4*)(csrc + 4 * j);

    for (int ck = 0; ck < 9; ck++) {
        const int cur = ck & 1;
        uint32_t* QP = (uint32_t*)(sm3 + K3_QP) + cur * 2304;
        uint32_t* CB = (uint32_t*)(sm3 + K3_CB) + cur * 2304;

        const int m0 = 32 * ck;
        float4 d[2], cc[2];
#pragma unroll
        for (int j = 0; j < 2; j++) { d[j] = pq[j]; cc[j] = pc[j]; }
        if (ck < 8) {
#pragma unroll
            for (int j = 0; j < 2; j++)
                pq[j] = *(const float4*)(qsrc + 32 * (ck + 1) + 4 * j);
#pragma unroll
            for (int j = 0; j < 2; j++)
                pc[j] = *(const float4*)(csrc + 32 * (ck + 1) + 4 * j);
        }
        // stage qp + D partial (8 m per thread)
#pragma unroll
        for (int j = 0; j < 2; j++) {
            const int mb = m0 + 8 * sq + 4 * j;
            float4 ks4 = *(float4*)&ksum_s[mb];
            float q0 = (mb < M_) ? RATIO_ * (__expf(d[j].x - qn - qm) + EPS_) : 0.f;
            float q1 = (mb + 1 < M_) ? RATIO_ * (__expf(d[j].y - qn - qm) + EPS_) : 0.f;
            float q2 = (mb + 2 < M_) ? RATIO_ * (__expf(d[j].z - qn - qm) + EPS_) : 0.f;
            float q3 = (mb + 3 < M_) ? RATIO_ * (__expf(d[j].w - qn - qm) + EPS_) : 0.f;
            Dpart += q0 * ks4.x + q1 * ks4.y + q2 * ks4.z + q3 * ks4.w;
            *(uint4*)&QP[sr * 36 + 8 * sq + 4 * j] =
                make_uint4(to_tf32(q0), to_tf32(q1), to_tf32(q2), to_tf32(q3));
        }
        // stage ctx (8 m per thread)
#pragma unroll
        for (int j = 0; j < 2; j++) {
            *(uint4*)&CB[sr * 36 + 8 * sq + 4 * j] =
                make_uint4(to_tf32(cc[j].x), to_tf32(cc[j].y),
                           to_tf32(cc[j].z), to_tf32(cc[j].w));
        }
        __syncthreads();
#pragma unroll
        for (int kk = 0; kk < 4; kk++) {
            const int c = 8 * kk + t;
            uint32_t a[4];
            a[0] = QP[(r_off + g) * 36 + c];
            a[1] = QP[(r_off + 8 + g) * 36 + c];
            a[2] = QP[(r_off + g) * 36 + c + 4];
            a[3] = QP[(r_off + 8 + g) * 36 + c + 4];
#pragma unroll
            for (int ni = 0; ni < 4; ni++) {
                const int cw = (e_off + 8 * ni + g) * 36;
                uint32_t b0 = CB[cw + c], b1 = CB[cw + c + 4];
                mma_tf32(acc[ni], a, b0, b1);
            }
        }
        __syncthreads();
    }

    // finish D^-1: 4 staging threads per row (consecutive lanes)
    Dpart += __shfl_xor_sync(0xffffffffu, Dpart, 1);
    Dpart += __shfl_xor_sync(0xffffffffu, Dpart, 2);
    if (sq == 0) dinv[sr] = 1.f / Dpart;
    __syncthreads();

#pragma unroll
    for (int ni = 0; ni < 4; ni++) {
        const int rl0 = r_off + g;
        const float di0 = dinv[rl0], di1 = dinv[rl0 + 8];
        const int col = e_off + 8 * ni + 2 * t;
        *(float2*)&OB[rl0 * 76 + col] =
            make_float2(acc[ni][0] * di0, acc[ni][1] * di0);
        *(float2*)&OB[(rl0 + 8) * 76 + col] =
            make_float2(acc[ni][2] * di1, acc[ni][3] * di1);
    }
    __syncthreads();
    for (int i = tid; i < 1024; i += 256) {
        const int r = i >> 4, c4 = i & 15;
        *(float4*)&out[((size_t)(bN + r0 + r)) * 64 + 4 * c4] =
            *(float4*)&OB[r * 76 + 4 * c4];
    }
}

// ---------------- launcher ----------------
extern "C" void kernel_launch(void* const* d_in, const int* in_sizes, int n_in,
                              void* d_out, int out_size) {
    const float* q    = (const float*)d_in[0];
    const float* k    = (const float*)d_in[1];
    const float* v    = (const float*)d_in[2];
    const float* proj = (const float*)d_in[3];
    float* out = (float*)d_out;

    static int configured = 0;
    if (!configured) {
        cudaFuncSetAttribute(k1_proj, cudaFuncAttributeMaxDynamicSharedMemorySize, K1_SM);
        cudaFuncSetAttribute(k3_out, cudaFuncAttributeMaxDynamicSharedMemorySize, K3_SM);
        configured = 1;
    }

    k1_proj<<<dim3(1024, 2, 2), 256, K1_SM>>>(q, k, proj);
    k1c_kmax<<<1, 256>>>();
    k2_ctx<<<dim3(3, 4, 64), 192>>>(v);
    kred<<<(B_ * 64 * MP_ / 4) / 256, 256>>>();
    k3_out<<<dim3(32, 64), 256, K3_SM>>>(out);
}

// round 16
// speedup vs baseline: 1.1376x; 1.1376x over previous
#include <cuda_runtime.h>
#include <cuda_bf16.h>
#include <cstdint>

// Performer (FAVOR+) attention. k1: bf16 split 3-MMA, 96-feat tiles + 3 CTAs/SM.
// k2/k3: tf32 single-MMA (R10 versions). B=64,N=2048,d=64,m=266(->288).

#define B_      64
#define N_      2048
#define D_      64
#define M_      266
#define MP_     288
#define NROWS_  (B_ * N_)
#define SCALE_  0.35355339059327373f
#define NORMC_  0.0625f
#define RATIO_  0.06131393394849658f
#define EPS_    1e-4f
#define CTXS_   ((size_t)B_ * 64 * MP_)

__device__ float    g_qdash[NROWS_ * MP_];
__device__ float    g_kdash[NROWS_ * MP_];
__device__ float    g_qnorm[NROWS_];
__device__ float    g_knorm[NROWS_];
__device__ float    g_qmax3[3 * NROWS_];
__device__ float    g_kpart[3072];
__device__ float    g_kmaxf;
__device__ float    g_ctxP[4 * B_ * 64 * MP_];
__device__ float    g_ksumP[4 * B_ * MP_];
__device__ float    g_ctx[B_ * 64 * MP_];
__device__ float    g_ksum[B_ * MP_];

// ---------------- helpers ----------------
__device__ __forceinline__ void mma_bf16(float* d, const uint32_t* a,
                                         uint32_t b0, uint32_t b1) {
    asm volatile(
        "mma.sync.aligned.m16n8k16.row.col.f32.bf16.bf16.f32 "
        "{%0,%1,%2,%3}, {%4,%5,%6,%7}, {%8,%9}, {%0,%1,%2,%3};\n"
        : "+f"(d[0]), "+f"(d[1]), "+f"(d[2]), "+f"(d[3])
        : "r"(a[0]), "r"(a[1]), "r"(a[2]), "r"(a[3]), "r"(b0), "r"(b1));
}
__device__ __forceinline__ void mma_tf32(float* d, const uint32_t* a,
                                         uint32_t b0, uint32_t b1) {
    asm volatile(
        "mma.sync.aligned.m16n8k8.row.col.f32.tf32.tf32.f32 "
        "{%0,%1,%2,%3}, {%4,%5,%6,%7}, {%8,%9}, {%0,%1,%2,%3};\n"
        : "+f"(d[0]), "+f"(d[1]), "+f"(d[2]), "+f"(d[3])
        : "r"(a[0]), "r"(a[1]), "r"(a[2]), "r"(a[3]), "r"(b0), "r"(b1));
}
__device__ __forceinline__ uint32_t to_tf32(float x) {
    uint32_t r;
    asm("cvt.rna.tf32.f32 %0, %1;" : "=r"(r) : "f"(x));
    return r;
}
__device__ __forceinline__ void split_pack(float x, float y, uint32_t& hi, uint32_t& lo) {
    __nv_bfloat16 hx = __float2bfloat16(x);
    __nv_bfloat16 hy = __float2bfloat16(y);
    __nv_bfloat16 lx = __float2bfloat16(x - __bfloat162float(hx));
    __nv_bfloat16 ly = __float2bfloat16(y - __bfloat162float(hy));
    hi = (uint32_t)__bfloat16_as_ushort(hx) | ((uint32_t)__bfloat16_as_ushort(hy) << 16);
    lo = (uint32_t)__bfloat16_as_ushort(lx) | ((uint32_t)__bfloat16_as_ushort(ly) << 16);
}
__device__ __forceinline__ uint32_t fenc(float x) {
    uint32_t u = __float_as_uint(x);
    return (u & 0x80000000u) ? ~u : (u | 0x80000000u);
}
__device__ __forceinline__ float fdec(uint32_t u) {
    return (u & 0x80000000u) ? __uint_as_float(u & 0x7FFFFFFFu) : __uint_as_float(~u);
}

// ---------------- K1: dash = SCALE * X @ P^T (96-feat tiles, 3 CTAs/SM) --------
// 8 warps (4r x 2f), warp tile 32x48 (2 m16 x 6 n8). acc = 48 regs.
#define K1_AH 0
#define K1_AL 18432
#define K1_BH 36864
#define K1_BL 50688
#define K1_RM 64512
#define K1_SM 65024

__global__ __launch_bounds__(256, 3)
void k1_proj(const float* __restrict__ Q, const float* __restrict__ K,
             const float* __restrict__ P) {
    extern __shared__ char sm[];
    uint32_t* Ah = (uint32_t*)(sm + K1_AH);
    uint32_t* Al = (uint32_t*)(sm + K1_AL);
    uint32_t* Bh = (uint32_t*)(sm + K1_BH);
    uint32_t* Bl = (uint32_t*)(sm + K1_BL);
    float*    OB = (float*)sm;                  // union after MMA (51200 B)
    uint32_t* rmaxU = (uint32_t*)(sm + K1_RM);

    const int tid = threadIdx.x, w = tid >> 5, l = tid & 31;
    const int g = l >> 2, t = l & 3;
    const int isq = (blockIdx.z == 0);
    const float* X = isq ? Q : K;
    const int row0 = blockIdx.x * 128;
    const int m0 = blockIdx.y * 96;
    const int r_off = (w & 3) * 32;
    const int f_off = (w >> 2) * 48;
    float* dash  = isq ? g_qdash : g_kdash;
    float* norms = isq ? g_qnorm : g_knorm;

    if (tid < 128) rmaxU[tid] = 0u;
    __syncthreads();

    const float4* X4 = (const float4*)X;
    for (int i = tid; i < 2048; i += 256) {
        const int r = i >> 4, c4 = i & 15;
        float4 v = X4[(size_t)(row0 + r) * 16 + c4];
        uint32_t h0, l0, h1, l1;
        split_pack(v.x, v.y, h0, l0);
        split_pack(v.z, v.w, h1, l1);
        Ah[r * 36 + 2 * c4] = h0; Ah[r * 36 + 2 * c4 + 1] = h1;
        Al[r * 36 + 2 * c4] = l0; Al[r * 36 + 2 * c4 + 1] = l1;
    }
    const float4* P4 = (const float4*)P;
    for (int i = tid; i < 1536; i += 256) {
        const int m = i >> 4, c4 = i & 15;
        float4 v = make_float4(0.f, 0.f, 0.f, 0.f);
        if (m0 + m < M_) v = P4[(size_t)(m0 + m) * 16 + c4];
        uint32_t h0, l0, h1, l1;
        split_pack(v.x * SCALE_, v.y * SCALE_, h0, l0);
        split_pack(v.z * SCALE_, v.w * SCALE_, h1, l1);
        Bh[m * 36 + 2 * c4] = h0; Bh[m * 36 + 2 * c4 + 1] = h1;
        Bl[m * 36 + 2 * c4] = l0; Bl[m * 36 + 2 * c4 + 1] = l1;
    }
    __syncthreads();

    if (blockIdx.y == 0 && tid < 128) {
        float s = 0.f;
        const float4* xr = X4 + (size_t)(row0 + tid) * 16;
#pragma unroll
        for (int c4 = 0; c4 < 16; c4++) {
            float4 v = xr[c4];
            s += v.x * v.x + v.y * v.y + v.z * v.z + v.w * v.w;
        }
        norms[row0 + tid] = NORMC_ * s;
    }

    float acc[2][6][4];
#pragma unroll
    for (int mi = 0; mi < 2; mi++)
#pragma unroll
        for (int ni = 0; ni < 6; ni++)
#pragma unroll
            for (int j = 0; j < 4; j++) acc[mi][ni][j] = 0.f;

#pragma unroll
    for (int kk = 0; kk < 4; kk++) {
        const int c = 8 * kk + t;
        uint32_t ah[2][4], al[2][4];
#pragma unroll
        for (int mi = 0; mi < 2; mi++) {
            const int rA = r_off + 16 * mi;
            ah[mi][0] = Ah[(rA + g) * 36 + c];
            ah[mi][1] = Ah[(rA + 8 + g) * 36 + c];
            ah[mi][2] = Ah[(rA + g) * 36 + c + 4];
            ah[mi][3] = Ah[(rA + 8 + g) * 36 + c + 4];
            al[mi][0] = Al[(rA + g) * 36 + c];
            al[mi][1] = Al[(rA + 8 + g) * 36 + c];
            al[mi][2] = Al[(rA + g) * 36 + c + 4];
            al[mi][3] = Al[(rA + 8 + g) * 36 + c + 4];
        }
#pragma unroll
        for (int ni = 0; ni < 6; ni++) {
            const int cw = (f_off + 8 * ni + g) * 36;
            uint32_t bh0 = Bh[cw + c], bh1 = Bh[cw + c + 4];
            uint32_t bl0 = Bl[cw + c], bl1 = Bl[cw + c + 4];
#pragma unroll
            for (int mi = 0; mi < 2; mi++) {
                mma_bf16(acc[mi][ni], ah[mi], bh0, bh1);
                mma_bf16(acc[mi][ni], ah[mi], bl0, bl1);
                mma_bf16(acc[mi][ni], al[mi], bh0, bh1);
            }
        }
    }

    float rmx[2][2] = {{-3.4e38f, -3.4e38f}, {-3.4e38f, -3.4e38f}};
#pragma unroll
    for (int mi = 0; mi < 2; mi++)
#pragma unroll
        for (int ni = 0; ni < 6; ni++) {
            const int cb = m0 + f_off + 8 * ni + 2 * t;
            if (cb < M_) {
                rmx[mi][0] = fmaxf(rmx[mi][0], acc[mi][ni][0]);
                rmx[mi][1] = fmaxf(rmx[mi][1], acc[mi][ni][2]);
            }
            if (cb + 1 < M_) {
                rmx[mi][0] = fmaxf(rmx[mi][0], acc[mi][ni][1]);
                rmx[mi][1] = fmaxf(rmx[mi][1], acc[mi][ni][3]);
            }
        }
#pragma unroll
    for (int mi = 0; mi < 2; mi++) {
        atomicMax(&rmaxU[r_off + 16 * mi + g], fenc(rmx[mi][0]));
        atomicMax(&rmaxU[r_off + 16 * mi + 8 + g], fenc(rmx[mi][1]));
    }

    __syncthreads();
#pragma unroll
    for (int mi = 0; mi < 2; mi++) {
        const int rl = r_off + 16 * mi + g;
#pragma unroll
        for (int ni = 0; ni < 6; ni++) {
            const int cl = f_off + 8 * ni + 2 * t;
            *(float2*)&OB[rl * 100 + cl]       = make_float2(acc[mi][ni][0], acc[mi][ni][1]);
            *(float2*)&OB[(rl + 8) * 100 + cl] = make_float2(acc[mi][ni][2], acc[mi][ni][3]);
        }
    }
    __syncthreads();

    for (int i = tid; i < 3072; i += 256) {
        const int r = i / 24, c4 = i - 24 * r;
        *(float4*)&dash[(size_t)(row0 + r) * MP_ + m0 + 4 * c4] =
            *(float4*)&OB[r * 100 + 4 * c4];
    }

    if (isq) {
        if (tid < 128)
            g_qmax3[blockIdx.y * NROWS_ + row0 + tid] = fdec(rmaxU[tid]);
    } else {
        if (tid < 32) {
            uint32_t u = max(max(rmaxU[tid], rmaxU[tid + 32]),
                             max(rmaxU[tid + 64], rmaxU[tid + 96]));
#pragma unroll
            for (int o = 16; o; o >>= 1)
                u = max(u, __shfl_xor_sync(0xffffffffu, u, o));
            if (tid == 0) g_kpart[blockIdx.y * 1024 + blockIdx.x] = fdec(u);
        }
    }
}

// ---------------- K1c: global k max ----------------
__global__ void k1c_kmax() {
    __shared__ float sm[256];
    float mx = -3.4e38f;
    for (int i = threadIdx.x; i < 3072; i += 256) mx = fmaxf(mx, g_kpart[i]);
    sm[threadIdx.x] = mx;
    __syncthreads();
    for (int s = 128; s; s >>= 1) {
        if (threadIdx.x < s) sm[threadIdx.x] = fmaxf(sm[threadIdx.x], sm[threadIdx.x + s]);
        __syncthreads();
    }
    if (threadIdx.x == 0) g_kmaxf = sm[0];
}

// ---------------- K2: ctxP[slice] = v^T @ kp (tf32, double-buffered) -----------
__global__ __launch_bounds__(192)
void k2_ctx(const float* __restrict__ v) {
    __shared__ uint32_t VA[2][64 * 20];
    __shared__ uint32_t KB[2][96 * 20];
    __shared__ float kss[96];

    const int tid = threadIdx.x, w = tid >> 5, l = tid & 31;
    const int g = l >> 2, t = l & 3;
    const int b = blockIdx.z;
    const int m0 = blockIdx.x * 96;
    const int slice = blockIdx.y;
    const int nbase = slice * 512;
    const int bN = b * N_;
    const float kmax = g_kmaxf;

    const int mloc = l + 32 * (w % 3);
    const int sgrp = w / 3;
    const int mglob = m0 + mloc;
    const bool mval = mglob < M_;
    const int vg = w >> 1;
    const int ve = l + 32 * (w & 1);

    const int e_off = (w & 1) * 32;
    const int m_off = (w >> 1) * 32;

    if (tid < 96) kss[tid] = 0.f;

    float acc[2][4][4];
#pragma unroll
    for (int mi = 0; mi < 2; mi++)
#pragma unroll
        for (int ni = 0; ni < 4; ni++)
#pragma unroll
            for (int j = 0; j < 4; j++) acc[mi][ni][j] = 0.f;
    float kslocal = 0.f;

    float pd0[4], pd1[4], pn0[4], pn1[4], pv0[4], pv1[4];
#pragma unroll
    for (int ii = 0; ii < 4; ii++) {
        const int n = nbase + 2 * (4 * sgrp + ii);
        pd0[ii] = g_kdash[(size_t)(bN + n) * MP_ + mglob];
        pd1[ii] = g_kdash[(size_t)(bN + n + 1) * MP_ + mglob];
        pn0[ii] = g_knorm[bN + n];
        pn1[ii] = g_knorm[bN + n + 1];
    }
    if (w < 4) {
#pragma unroll
        for (int ii = 0; ii < 4; ii++) {
            const int n = nbase + 2 * (4 * vg + ii);
            pv0[ii] = v[(size_t)(bN + n) * 64 + ve];
            pv1[ii] = v[(size_t)(bN + n + 1) * 64 + ve];
        }
    }

    for (int ck = 0; ck < 32; ck++) {
        const int cur = ck & 1;
        uint32_t* va = VA[cur];
        uint32_t* kb = KB[cur];

        float d0c[4], d1c[4], n0c[4], n1c[4], v0c[4], v1c[4];
#pragma unroll
        for (int ii = 0; ii < 4; ii++) {
            d0c[ii] = pd0[ii]; d1c[ii] = pd1[ii];
            n0c[ii] = pn0[ii]; n1c[ii] = pn1[ii];
            v0c[ii] = pv0[ii]; v1c[ii] = pv1[ii];
        }
        if (ck < 31) {
            const int nn = nbase + 16 * (ck + 1);
#pragma unroll
            for (int ii = 0; ii < 4; ii++) {
                const int n = nn + 2 * (4 * sgrp + ii);
                pd0[ii] = g_kdash[(size_t)(bN + n) * MP_ + mglob];
                pd1[ii] = g_kdash[(size_t)(bN + n + 1) * MP_ + mglob];
                pn0[ii] = g_knorm[bN + n];
                pn1[ii] = g_knorm[bN + n + 1];
            }
            if (w < 4) {
#pragma unroll
                for (int ii = 0; ii < 4; ii++) {
                    const int n = nn + 2 * (4 * vg + ii);
                    pv0[ii] = v[(size_t)(bN + n) * 64 + ve];
                    pv1[ii] = v[(size_t)(bN + n + 1) * 64 + ve];
                }
            }
        }
#pragma unroll
        for (int ii = 0; ii < 4; ii++) {
            const int i = 4 * sgrp + ii;
            float kp0 = mval ? RATIO_ * (__expf(d0c[ii] - n0c[ii] - kmax) + EPS_) : 0.f;
            float kp1 = mval ? RATIO_ * (__expf(d1c[ii] - n1c[ii] - kmax) + EPS_) : 0.f;
            kslocal += kp0 + kp1;
            *(uint2*)&kb[mloc * 20 + 2 * i] = make_uint2(to_tf32(kp0), to_tf32(kp1));
        }
        if (w < 4) {
#pragma unroll
            for (int ii = 0; ii < 4; ii++) {
                const int i = 4 * vg + ii;
                *(uint2*)&va[ve * 20 + 2 * i] = make_uint2(to_tf32(v0c[ii]), to_tf32(v1c[ii]));
            }
        }
        __syncthreads();
#pragma unroll
        for (int kk = 0; kk < 2; kk++) {
            const int c = 8 * kk + t;
            uint32_t a[2][4];
#pragma unroll
            for (int mi = 0; mi < 2; mi++) {
                const int eR = e_off + 16 * mi;
                a[mi][0] = va[(eR + g) * 20 + c];
                a[mi][1] = va[(eR + 8 + g) * 20 + c];
                a[mi][2] = va[(eR + g) * 20 + c + 4];
                a[mi][3] = va[(eR + 8 + g) * 20 + c + 4];
            }
#pragma unroll
            for (int ni = 0; ni < 4; ni++) {
                const int cw = (m_off + 8 * ni + g) * 20;
                uint32_t b0 = kb[cw + c], b1 = kb[cw + c + 4];
#pragma unroll
                for (int mi = 0; mi < 2; mi++)
                    mma_tf32(acc[mi][ni], a[mi], b0, b1);
            }
        }
    }

    atomicAdd(&kss[mloc], kslocal);
    __syncthreads();
    if (tid < 96) g_ksumP[((size_t)(slice * B_ + b)) * MP_ + m0 + tid] = kss[tid];

    float* base = g_ctxP + slice * CTXS_;
#pragma unroll
    for (int mi = 0; mi < 2; mi++) {
        const int e0 = e_off + 16 * mi + g;
#pragma unroll
        for (int ni = 0; ni < 4; ni++) {
            const int mc = m0 + m_off + 8 * ni + 2 * t;
            *(float2*)&base[((size_t)(b * 64 + e0)) * MP_ + mc] =
                make_float2(acc[mi][ni][0], acc[mi][ni][1]);
            *(float2*)&base[((size_t)(b * 64 + e0 + 8)) * MP_ + mc] =
                make_float2(acc[mi][ni][2], acc[mi][ni][3]);
        }
    }
}

// ---------------- KRED: ctx = sum(ctxP), ksum = sum(ksumP) ----------------------
__global__ void kred() {
    const int i = blockIdx.x * 256 + threadIdx.x;
    const float4* s0 = (const float4*)g_ctxP;
    float4 a = s0[i];
    float4 b = s0[i + CTXS_ / 4];
    float4 c = s0[i + 2 * (CTXS_ / 4)];
    float4 d = s0[i + 3 * (CTXS_ / 4)];
    ((float4*)g_ctx)[i] = make_float4(a.x + b.x + c.x + d.x, a.y + b.y + c.y + d.y,
                                      a.z + b.z + c.z + d.z, a.w + b.w + c.w + d.w);
    if (i < B_ * MP_ / 4) {
        const float4* k0 = (const float4*)g_ksumP;
        const int st = B_ * MP_ / 4;
        float4 e = k0[i], f = k0[i + st], g = k0[i + 2 * st], h = k0[i + 3 * st];
        ((float4*)g_ksum)[i] = make_float4(e.x + f.x + g.x + h.x, e.y + f.y + g.y + h.y,
                                           e.z + f.z + g.z + h.z, e.w + f.w + g.w + h.w);
    }
}

// ---------------- K3: out = (qp @ ctx^T) * dinv (tf32, double-buffered) --------
#define K3_QP  0
#define K3_CB  36864
#define K3_DI  55296
#define K3_KS  55808
#define K3_SM  56960

__global__ __launch_bounds__(256)
void k3_out(float* __restrict__ out) {
    extern __shared__ char sm3[];
    float* OB   = (float*)sm3;
    float* dinv = (float*)(sm3 + K3_DI);
    float* ksum_s = (float*)(sm3 + K3_KS);

    const int tid = threadIdx.x, w = tid >> 5, l = tid & 31;
    const int g = l >> 2, t = l & 3;
    const int b = blockIdx.y;
    const int r0 = blockIdx.x * 128;
    const int bN = b * N_;

    const int sr = tid >> 1, shalf = tid & 1;
    const int se = tid >> 2, sq4 = tid & 3;

    const int gr = bN + r0 + sr;
    const float qn = g_qnorm[gr];
    const float qm = fmaxf(fmaxf(g_qmax3[gr], g_qmax3[NROWS_ + gr]),
                           g_qmax3[2 * NROWS_ + gr]);

    const int r_off = (w & 3) * 32;
    const int e_off = (w >> 2) * 32;

    for (int i = tid; i < MP_; i += 256) ksum_s[i] = g_ksum[b * MP_ + i];
    __syncthreads();

    float acc[2][4][4];
#pragma unroll
    for (int mi = 0; mi < 2; mi++)
#pragma unroll
        for (int ni = 0; ni < 4; ni++)
#pragma unroll
            for (int j = 0; j < 4; j++) acc[mi][ni][j] = 0.f;
    float Dpart = 0.f;

    const float* qsrc = g_qdash + (size_t)gr * MP_ + 16 * shalf;
    const float* csrc = g_ctx + ((size_t)(b * 64 + se)) * MP_ + 8 * sq4;

    float4 pq[4], pc[2];
#pragma unroll
    for (int j = 0; j < 4; j++) pq[j] = *(const float4*)(qsrc + 4 * j);
#pragma unroll
    for (int j = 0; j < 2; j++) pc[j] = *(const float4*)(csrc + 4 * j);

    for (int ck = 0; ck < 9; ck++) {
        const int cur = ck & 1;
        uint32_t* QP = (uint32_t*)(sm3 + K3_QP) + cur * 4608;
        uint32_t* CB = (uint32_t*)(sm3 + K3_CB) + cur * 2304;

        const int m0 = 32 * ck;
        float4 d[4], cc[2];
#pragma unroll
        for (int j = 0; j < 4; j++) d[j] = pq[j];
#pragma unroll
        for (int j = 0; j < 2; j++) cc[j] = pc[j];
        if (ck < 8) {
#pragma unroll
            for (int j = 0; j < 4; j++)
                pq[j] = *(const float4*)(qsrc + 32 * (ck + 1) + 4 * j);
#pragma unroll
            for (int j = 0; j < 2; j++)
                pc[j] = *(const float4*)(csrc + 32 * (ck + 1) + 4 * j);
        }
        {
#pragma unroll
            for (int j = 0; j < 4; j++) {
                const int mb = m0 + 16 * shalf + 4 * j;
                float4 ks4 = *(float4*)&ksum_s[mb];
                float q0 = (mb < M_) ? RATIO_ * (__expf(d[j].x - qn - qm) + EPS_) : 0.f;
                float q1 = (mb + 1 < M_) ? RATIO_ * (__expf(d[j].y - qn - qm) + EPS_) : 0.f;
                float q2 = (mb + 2 < M_) ? RATIO_ * (__expf(d[j].z - qn - qm) + EPS_) : 0.f;
                float q3 = (mb + 3 < M_) ? RATIO_ * (__expf(d[j].w - qn - qm) + EPS_) : 0.f;
                Dpart += q0 * ks4.x + q1 * ks4.y + q2 * ks4.z + q3 * ks4.w;
                *(uint4*)&QP[sr * 36 + 16 * shalf + 4 * j] =
                    make_uint4(to_tf32(q0), to_tf32(q1), to_tf32(q2), to_tf32(q3));
            }
        }
#pragma unroll
        for (int j = 0; j < 2; j++) {
            *(uint4*)&CB[se * 36 + 8 * sq4 + 4 * j] =
                make_uint4(to_tf32(cc[j].x), to_tf32(cc[j].y),
                           to_tf32(cc[j].z), to_tf32(cc[j].w));
        }
        __syncthreads();
#pragma unroll
        for (int kk = 0; kk < 4; kk++) {
            const int c = 8 * kk + t;
            uint32_t a[2][4];
#pragma unroll
            for (int mi = 0; mi < 2; mi++) {
                const int rA = r_off + 16 * mi;
                a[mi][0] = QP[(rA + g) * 36 + c];
                a[mi][1] = QP[(rA + 8 + g) * 36 + c];
                a[mi][2] = QP[(rA + g) * 36 + c + 4];
                a[mi][3] = QP[(rA + 8 + g) * 36 + c + 4];
            }
#pragma unroll
            for (int ni = 0; ni < 4; ni++) {
                const int cw = (e_off + 8 * ni + g) * 36;
                uint32_t b0 = CB[cw + c], b1 = CB[cw + c + 4];
#pragma unroll
                for (int mi = 0; mi < 2; mi++)
                    mma_tf32(acc[mi][ni], a[mi], b0, b1);
            }
        }
        __syncthreads();
    }

    Dpart += __shfl_xor_sync(0xffffffffu, Dpart, 1);
    if ((tid & 1) == 0) dinv[sr] = 1.f / Dpart;
    __syncthreads();

#pragma unroll
    for (int mi = 0; mi < 2; mi++) {
        const int rl0 = r_off + 16 * mi + g;
        const float di0 = dinv[rl0], di1 = dinv[rl0 + 8];
#pragma unroll
        for (int ni = 0; ni < 4; ni++) {
            const int col = e_off + 8 * ni + 2 * t;
            *(float2*)&OB[rl0 * 76 + col] =
                make_float2(acc[mi][ni][0] * di0, acc[mi][ni][1] * di0);
            *(float2*)&OB[(rl0 + 8) * 76 + col] =
                make_float2(acc[mi][ni][2] * di1, acc[mi][ni][3] * di1);
        }
    }
    __syncthreads();
    for (int i = tid; i < 2048; i += 256) {
        const int r = i >> 4, c4 = i & 15;
        *(float4*)&out[((size_t)(bN + r0 + r)) * 64 + 4 * c4] =
            *(float4*)&OB[r * 76 + 4 * c4];
    }
}

// ---------------- launcher ----------------
extern "C" void kernel_launch(void* const* d_in, const int* in_sizes, int n_in,
                              void* d_out, int out_size) {
    const float* q    = (const float*)d_in[0];
    const float* k    = (const float*)d_in[1];
    const float* v    = (const float*)d_in[2];
    const float* proj = (const float*)d_in[3];
    float* out = (float*)d_out;

    static int configured = 0;
    if (!configured) {
        cudaFuncSetAttribute(k1_proj, cudaFuncAttributeMaxDynamicSharedMemorySize, K1_SM);
        cudaFuncSetAttribute(k3_out, cudaFuncAttributeMaxDynamicSharedMemorySize, K3_SM);
        configured = 1;
    }

    k1_proj<<<dim3(1024, 3, 2), 256, K1_SM>>>(q, k, proj);
    k1c_kmax<<<1, 256>>>();
    k2_ctx<<<dim3(3, 4, 64), 192>>>(v);
    kred<<<(B_ * 64 * MP_ / 4) / 256, 256>>>();
    k3_out<<<dim3(16, 64), 256, K3_SM>>>(out);
}